// round 14
// baseline (speedup 1.0000x reference)
#include <cuda_runtime.h>
#include <cuda_bf16.h>
#include <cstdint>

#define N_P   200000
#define N_A   100000
#define D_MP  64
#define E_NNZ 1200000
#define F_P   256
#define F_A   128

// ===========================================================================
// Static scratch
// ===========================================================================
__device__ __align__(16) float g_bufP [(size_t)N_P * D_MP];   // zp
__device__ __align__(16) float g_bufG [(size_t)N_P * D_MP];   // g (apa chain)
__device__ __align__(16) float g_bufA1[(size_t)N_A * D_MP];   // za
__device__ __align__(16) float g_bufA2[(size_t)N_A * D_MP];   // h, later h2

__device__ __align__(16) uint2 g_WsplitP[(F_P / 32) * 1024];
__device__ __align__(16) uint2 g_WsplitA[(F_A / 32) * 1024];

__device__ int   g_pa_ptr[N_A + 1];
__device__ int   g_ap_ptr[N_P + 1];
__device__ int   g_pa_ccol[E_NNZ];
__device__ float g_pa_cval[E_NNZ];
__device__ int   g_ap_ccol[E_NNZ];
__device__ float g_ap_cval[E_NNZ];
__device__ int   g_cnt[2 * (N_P + N_A)];
__device__ int   g_bsumA[128];
__device__ int   g_bsumP[128];

// ===========================================================================
// bf16 split helpers
// ===========================================================================
__device__ __forceinline__ uint2 split_pack(float a, float b) {
    float fa = __bfloat162float(__float2bfloat16_rn(a));
    float fb = __bfloat162float(__float2bfloat16_rn(b));
    uint32_t hi, lo;
    asm("cvt.rn.bf16x2.f32 %0, %1, %2;" : "=r"(hi) : "f"(fb), "f"(fa));
    asm("cvt.rn.bf16x2.f32 %0, %1, %2;" : "=r"(lo) : "f"(b - fb), "f"(a - fa));
    return make_uint2(hi, lo);
}

__device__ __forceinline__ void mma_bf16(float* d, const uint32_t* a, const uint32_t* b) {
    asm volatile("mma.sync.aligned.m16n8k16.row.col.f32.bf16.bf16.f32 "
                 "{%0,%1,%2,%3}, {%4,%5,%6,%7}, {%8,%9}, {%0,%1,%2,%3};"
                 : "+f"(d[0]), "+f"(d[1]), "+f"(d[2]), "+f"(d[3])
                 : "r"(a[0]), "r"(a[1]), "r"(a[2]), "r"(a[3]),
                   "r"(b[0]), "r"(b[1]));
}

// ===========================================================================
// Prep: split W into chunked smem-image layout
// ===========================================================================
__global__ void prep_W(const float* __restrict__ W, uint2* __restrict__ dst, int F) {
    int i = blockIdx.x * blockDim.x + threadIdx.x;
    int total = (F / 32) * 1024;
    if (i >= total) return;
    int chunk = i >> 10;
    int idx   = i & 1023;
    int nn = idx & 63;
    int kp = idx >> 6;
    int k  = chunk * 32 + kp * 2;
    float w0 = W[(size_t)k * 64 + nn];
    float w1 = W[(size_t)(k + 1) * 64 + nn];
    dst[i] = split_pack(w0, w1);
}

// ===========================================================================
// Tensor-core GEMM (R10/R11 proven config)
// ===========================================================================
template<int F>
__global__ __launch_bounds__(256, 2) void gemm_bf16x3(const float* __restrict__ x,
                                                      const uint2* __restrict__ Wsp,
                                                      float* __restrict__ out, int n) {
    constexpr int NC = F / 32;
    extern __shared__ uint2 smbuf[];
    uint2* wsb[2] = { smbuf,            smbuf + 64 * 20 };
    uint2* xsb[2] = { smbuf + 2 * 64 * 20, smbuf + 2 * 64 * 20 + 128 * 20 };

    const int t    = threadIdx.x;
    const int lane = t & 31;
    const int wid  = t >> 5;
    const int wm   = wid >> 1;
    const int wn   = wid & 1;
    const int tig  = lane & 3;
    const int gid  = lane >> 2;
    const int row0 = blockIdx.x * 128;

    float2 xreg[8];
    uint2  wreg[4];

    auto ldg_chunk = [&](int c) {
        const uint2* src = Wsp + c * 1024;
        #pragma unroll
        for (int j = 0; j < 4; j++) wreg[j] = __ldg(src + j * 256 + t);
        #pragma unroll
        for (int j = 0; j < 8; j++) {
            int idx = j * 256 + t;
            int r   = idx >> 4;
            int kp  = idx & 15;
            int grow = row0 + r;
            xreg[j] = (grow < n)
                ? *(const float2*)(x + (size_t)grow * F + c * 32 + kp * 2)
                : make_float2(0.f, 0.f);
        }
    };
    auto sts_chunk = [&](int b) {
        #pragma unroll
        for (int j = 0; j < 4; j++) {
            int idx = j * 256 + t;
            wsb[b][(idx & 63) * 20 + (idx >> 6)] = wreg[j];
        }
        #pragma unroll
        for (int j = 0; j < 8; j++) {
            int idx = j * 256 + t;
            xsb[b][(idx >> 4) * 20 + (idx & 15)] = split_pack(xreg[j].x, xreg[j].y);
        }
    };

    float acc[2][4][4];
    #pragma unroll
    for (int mt = 0; mt < 2; mt++)
        #pragma unroll
        for (int nt = 0; nt < 4; nt++)
            #pragma unroll
            for (int q = 0; q < 4; q++) acc[mt][nt][q] = 0.f;

    ldg_chunk(0);
    sts_chunk(0);
    if (NC > 1) ldg_chunk(1);
    __syncthreads();

    #pragma unroll
    for (int c = 0; c < NC; c++) {
        if (c + 1 < NC) sts_chunk((c + 1) & 1);
        if (c + 2 < NC) ldg_chunk(c + 2);

        const uint2* xs = xsb[c & 1];
        const uint2* ws = wsb[c & 1];

        #pragma unroll
        for (int ks = 0; ks < 2; ks++) {
            const int p0 = ks * 8 + tig;
            const int p1 = p0 + 4;

            uint32_t ah[2][4], al[2][4];
            #pragma unroll
            for (int mt = 0; mt < 2; mt++) {
                int r0 = wm * 32 + mt * 16 + gid;
                uint2 qa0 = xs[r0 * 20 + p0];
                uint2 qa1 = xs[(r0 + 8) * 20 + p0];
                uint2 qa2 = xs[r0 * 20 + p1];
                uint2 qa3 = xs[(r0 + 8) * 20 + p1];
                ah[mt][0] = qa0.x; ah[mt][1] = qa1.x; ah[mt][2] = qa2.x; ah[mt][3] = qa3.x;
                al[mt][0] = qa0.y; al[mt][1] = qa1.y; al[mt][2] = qa2.y; al[mt][3] = qa3.y;
            }

            #pragma unroll
            for (int nt = 0; nt < 4; nt++) {
                int nn = wn * 32 + nt * 8 + gid;
                uint2 qb0 = ws[nn * 20 + p0];
                uint2 qb1 = ws[nn * 20 + p1];
                uint32_t bh[2] = {qb0.x, qb1.x};
                uint32_t bl[2] = {qb0.y, qb1.y};
                #pragma unroll
                for (int mt = 0; mt < 2; mt++) {
                    mma_bf16(acc[mt][nt], ah[mt], bh);
                    mma_bf16(acc[mt][nt], al[mt], bh);
                    mma_bf16(acc[mt][nt], ah[mt], bl);
                }
            }
        }
        __syncthreads();
    }

    #pragma unroll
    for (int mt = 0; mt < 2; mt++) {
        #pragma unroll
        for (int half = 0; half < 2; half++) {
            int grow = row0 + wm * 32 + mt * 16 + gid + half * 8;
            if (grow < n) {
                float* o = out + (size_t)grow * D_MP + wn * 32 + tig * 2;
                #pragma unroll
                for (int nt = 0; nt < 4; nt++) {
                    float2 v = half ? make_float2(acc[mt][nt][2], acc[mt][nt][3])
                                    : make_float2(acc[mt][nt][0], acc[mt][nt][1]);
                    *(float2*)(o + nt * 8) = v;
                }
            }
        }
    }
}

// ===========================================================================
// CSR build
// ===========================================================================
__global__ void hist_dual(const int* __restrict__ rowA, const int* __restrict__ rowP,
                          int* __restrict__ cntA, int* __restrict__ cntP) {
    int i = blockIdx.x * blockDim.x + threadIdx.x;
    if (i < E_NNZ) {
        atomicAdd(&cntA[rowA[i]], 1);
    } else if (i < 2 * E_NNZ) {
        atomicAdd(&cntP[rowP[i - E_NNZ]], 1);
    }
}

#define SCAN_CHUNK 2048

__global__ void scan_pass1_dual(const int* __restrict__ cntA, int* __restrict__ bsA, int nA,
                                const int* __restrict__ cntP, int* __restrict__ bsP, int nP,
                                int nbA) {
    __shared__ int sh[256];
    const int* cnt = (blockIdx.x < nbA) ? cntA : cntP;
    int*       bs  = (blockIdx.x < nbA) ? bsA  : bsP;
    int        n   = (blockIdx.x < nbA) ? nA   : nP;
    int        blk = (blockIdx.x < nbA) ? blockIdx.x : blockIdx.x - nbA;
    int base = blk * SCAN_CHUNK;
    int t = threadIdx.x;
    int s = 0;
    #pragma unroll
    for (int j = 0; j < 8; j++) {
        int i = base + t * 8 + j;
        if (i < n) s += cnt[i];
    }
    sh[t] = s;
    __syncthreads();
    for (int off = 128; off > 0; off >>= 1) {
        if (t < off) sh[t] += sh[t + off];
        __syncthreads();
    }
    if (t == 0) bs[blk] = sh[0];
}

__global__ void scan_pass2_dual(int* __restrict__ bsA, int nbA,
                                int* __restrict__ bsP, int nbP) {
    __shared__ int sh[128];
    int* bs = blockIdx.x ? bsP : bsA;
    int nb  = blockIdx.x ? nbP : nbA;
    int t = threadIdx.x;
    int v = (t < nb) ? bs[t] : 0;
    sh[t] = v;
    __syncthreads();
    for (int off = 1; off < 128; off <<= 1) {
        int xx = (t >= off) ? sh[t - off] : 0;
        __syncthreads();
        sh[t] += xx;
        __syncthreads();
    }
    if (t < nb) bs[t] = sh[t] - v;
}

__global__ void scan_pass3_dual(const int* __restrict__ cntA, const int* __restrict__ bsA,
                                int* __restrict__ ptrA, int nA,
                                const int* __restrict__ cntP, const int* __restrict__ bsP,
                                int* __restrict__ ptrP, int nP, int nbA) {
    __shared__ int sh[256];
    const int* cnt = (blockIdx.x < nbA) ? cntA : cntP;
    const int* bs  = (blockIdx.x < nbA) ? bsA  : bsP;
    int*       ptr = (blockIdx.x < nbA) ? ptrA : ptrP;
    int        n   = (blockIdx.x < nbA) ? nA   : nP;
    int        blk = (blockIdx.x < nbA) ? blockIdx.x : blockIdx.x - nbA;
    int base = blk * SCAN_CHUNK;
    int t = threadIdx.x;
    int v[8];
    int s = 0;
    #pragma unroll
    for (int j = 0; j < 8; j++) {
        int i = base + t * 8 + j;
        v[j] = (i < n) ? cnt[i] : 0;
        s += v[j];
    }
    sh[t] = s;
    __syncthreads();
    for (int off = 1; off < 256; off <<= 1) {
        int xx = (t >= off) ? sh[t - off] : 0;
        __syncthreads();
        sh[t] += xx;
        __syncthreads();
    }
    int ex = sh[t] - s + bs[blk];
    #pragma unroll
    for (int j = 0; j < 8; j++) {
        int i = base + t * 8 + j;
        if (i < n) {
            ptr[i] = ex;
            ex += v[j];
            if (i == n - 1) ptr[n] = ex;
        }
    }
}

__global__ void scatter_dual(const int* __restrict__ rowA, const int* __restrict__ colA,
                             const float* __restrict__ valA,
                             const int* __restrict__ ptrA, int* __restrict__ curA,
                             int* __restrict__ ccolA, float* __restrict__ cvalA,
                             const int* __restrict__ rowP, const int* __restrict__ colP,
                             const float* __restrict__ valP,
                             const int* __restrict__ ptrP, int* __restrict__ curP,
                             int* __restrict__ ccolP, float* __restrict__ cvalP) {
    int i = blockIdx.x * blockDim.x + threadIdx.x;
    if (i < E_NNZ) {
        int r = rowA[i];
        int p = ptrA[r] + atomicAdd(&curA[r], 1);
        ccolA[p] = colA[i];
        cvalA[p] = valA[i];
    } else if (i < 2 * E_NNZ) {
        int j = i - E_NNZ;
        int r = rowP[j];
        int p = ptrP[r] + atomicAdd(&curP[r], 1);
        ccolP[p] = colP[j];
        cvalP[p] = valP[j];
    }
}

// ===========================================================================
// CSR SpMM v2: warp per row, 4 x 8-lane groups, each group takes every 4th
// edge and loads the full 64-col z row as 2 float4/lane -> 8 independent
// gathers in flight per warp (2x the R11 MLP). Cross-group reduce: 2 shfls.
// ===========================================================================
__global__ void spmm_csr_kernel(const int* __restrict__ ptr,
                                const int* __restrict__ ccol,
                                const float* __restrict__ cval,
                                const float* __restrict__ z,
                                float* __restrict__ out, int nrows) {
    int w = (blockIdx.x * blockDim.x + threadIdx.x) >> 5;
    if (w >= nrows) return;
    int lane = threadIdx.x & 31;
    int g  = lane >> 3;     // group 0..3
    int l8 = lane & 7;      // lane within group

    int beg = ptr[w], end = ptr[w + 1];
    float4 a0 = make_float4(0.f, 0.f, 0.f, 0.f);
    float4 a1 = make_float4(0.f, 0.f, 0.f, 0.f);

    for (int e = beg + g; e < end; e += 4) {
        int   c = __ldg(ccol + e);
        float v = __ldg(cval + e);
        const float4* zr = (const float4*)(z + (size_t)c * D_MP);
        float4 q0 = __ldg(zr + l8);
        float4 q1 = __ldg(zr + 8 + l8);
        a0.x = fmaf(v, q0.x, a0.x);
        a0.y = fmaf(v, q0.y, a0.y);
        a0.z = fmaf(v, q0.z, a0.z);
        a0.w = fmaf(v, q0.w, a0.w);
        a1.x = fmaf(v, q1.x, a1.x);
        a1.y = fmaf(v, q1.y, a1.y);
        a1.z = fmaf(v, q1.z, a1.z);
        a1.w = fmaf(v, q1.w, a1.w);
    }

    // reduce across the 4 groups (lanes differing by 8 and 16)
    #pragma unroll
    for (int off = 8; off <= 16; off <<= 1) {
        a0.x += __shfl_xor_sync(0xffffffffu, a0.x, off);
        a0.y += __shfl_xor_sync(0xffffffffu, a0.y, off);
        a0.z += __shfl_xor_sync(0xffffffffu, a0.z, off);
        a0.w += __shfl_xor_sync(0xffffffffu, a0.w, off);
        a1.x += __shfl_xor_sync(0xffffffffu, a1.x, off);
        a1.y += __shfl_xor_sync(0xffffffffu, a1.y, off);
        a1.z += __shfl_xor_sync(0xffffffffu, a1.z, off);
        a1.w += __shfl_xor_sync(0xffffffffu, a1.w, off);
    }

    if (g == 0) {
        float4* o = (float4*)(out + (size_t)w * D_MP);
        o[l8]     = a0;
        o[8 + l8] = a1;
    }
}

// ===========================================================================
// Launch — exact R11 schedule (proven 415.6): s2 = CSR build, s3 = gemm A
// concurrent with gemm P, then concurrent pap/apa chains.
// ===========================================================================
extern "C" void kernel_launch(void* const* d_in, const int* in_sizes, int n_in,
                              void* d_out, int out_size) {
    const float* x_paper  = (const float*)d_in[0];
    const float* x_author = (const float*)d_in[1];
    const float* W_paper  = (const float*)d_in[2];
    const float* W_author = (const float*)d_in[3];
    const int*   pa_row   = (const int*)  d_in[4];
    const int*   pa_col   = (const int*)  d_in[5];
    const float* pa_val   = (const float*)d_in[6];
    const int*   ap_row   = (const int*)  d_in[7];
    const int*   ap_col   = (const int*)  d_in[8];
    const float* ap_val   = (const float*)d_in[9];

    float* out       = (float*)d_out;
    float* out_pap   = out;
    float* out_papap = out + (size_t)N_P * D_MP;
    float* out_apa   = out + (size_t)2 * N_P * D_MP;

    float *bufP, *bufG, *bufA1, *bufA2;
    uint2 *WspP, *WspA;
    int *pa_ptr, *ap_ptr, *pa_ccol, *ap_ccol, *cnt, *bsumA, *bsumP;
    float *pa_cval, *ap_cval;
    cudaGetSymbolAddress((void**)&bufP,    g_bufP);
    cudaGetSymbolAddress((void**)&bufG,    g_bufG);
    cudaGetSymbolAddress((void**)&bufA1,   g_bufA1);
    cudaGetSymbolAddress((void**)&bufA2,   g_bufA2);
    cudaGetSymbolAddress((void**)&WspP,    g_WsplitP);
    cudaGetSymbolAddress((void**)&WspA,    g_WsplitA);
    cudaGetSymbolAddress((void**)&pa_ptr,  g_pa_ptr);
    cudaGetSymbolAddress((void**)&ap_ptr,  g_ap_ptr);
    cudaGetSymbolAddress((void**)&pa_ccol, g_pa_ccol);
    cudaGetSymbolAddress((void**)&pa_cval, g_pa_cval);
    cudaGetSymbolAddress((void**)&ap_ccol, g_ap_ccol);
    cudaGetSymbolAddress((void**)&ap_cval, g_ap_cval);
    cudaGetSymbolAddress((void**)&cnt,     g_cnt);
    cudaGetSymbolAddress((void**)&bsumA,   g_bsumA);
    cudaGetSymbolAddress((void**)&bsumP,   g_bsumP);

    int* cntA = cnt;
    int* curA = cnt + N_A;
    int* cntP = cnt + 2 * N_A;
    int* curP = cnt + 2 * N_A + N_P;

    static cudaStream_t s2 = nullptr, s3 = nullptr;
    static cudaEvent_t eFork, eCsr, ePrep, eApa;
    if (s2 == nullptr) {
        cudaStreamCreateWithFlags(&s2, cudaStreamNonBlocking);
        cudaStreamCreateWithFlags(&s3, cudaStreamNonBlocking);
        cudaEventCreateWithFlags(&eFork, cudaEventDisableTiming);
        cudaEventCreateWithFlags(&eCsr,  cudaEventDisableTiming);
        cudaEventCreateWithFlags(&ePrep, cudaEventDisableTiming);
        cudaEventCreateWithFlags(&eApa,  cudaEventDisableTiming);
    }

    const int GEMM_SMEM = (2 * 64 * 20 + 2 * 128 * 20) * (int)sizeof(uint2);  // 61440
    cudaFuncSetAttribute(gemm_bf16x3<F_P>, cudaFuncAttributeMaxDynamicSharedMemorySize, GEMM_SMEM);
    cudaFuncSetAttribute(gemm_bf16x3<F_A>, cudaFuncAttributeMaxDynamicSharedMemorySize, GEMM_SMEM);

    const int HB = 256;
    const int dgrid = (2 * E_NNZ + HB - 1) / HB;
    const int nbA = (N_A + SCAN_CHUNK - 1) / SCAN_CHUNK;
    const int nbP = (N_P + SCAN_CHUNK - 1) / SCAN_CHUNK;
    auto sblocks = [](int nrows) { return (nrows * 32 + 255) / 256; };

    // ---- fork ----
    cudaEventRecord(eFork, 0);
    cudaStreamWaitEvent(s2, eFork, 0);
    cudaStreamWaitEvent(s3, eFork, 0);

    // ---- s2: CSR build (hidden under GEMMs) ----
    cudaMemsetAsync(cnt, 0, (size_t)2 * (N_P + N_A) * sizeof(int), s2);

    // main: W prep
    prep_W<<<(F_P / 32 * 1024 + 255) / 256, 256>>>(W_paper,  WspP, F_P);
    prep_W<<<(F_A / 32 * 1024 + 255) / 256, 256>>>(W_author, WspA, F_A);
    cudaEventRecord(ePrep, 0);
    cudaStreamWaitEvent(s3, ePrep, 0);

    // s2: hist
    hist_dual<<<dgrid, HB, 0, s2>>>(pa_row, ap_row, cntA, cntP);

    // main: gemm P (ncu capture slot 3); s3: gemm A concurrent
    gemm_bf16x3<F_P><<<(N_P + 127) / 128, 256, GEMM_SMEM>>>(x_paper, WspP, bufP, N_P);
    gemm_bf16x3<F_A><<<(N_A + 127) / 128, 256, GEMM_SMEM, s3>>>(x_author, WspA, bufA1, N_A);

    // s2: rest of CSR build
    scan_pass1_dual<<<nbA + nbP, 256, 0, s2>>>(cntA, bsumA, N_A, cntP, bsumP, N_P, nbA);
    scan_pass2_dual<<<2, 128, 0, s2>>>(bsumA, nbA, bsumP, nbP);
    scan_pass3_dual<<<nbA + nbP, 256, 0, s2>>>(cntA, bsumA, pa_ptr, N_A,
                                               cntP, bsumP, ap_ptr, N_P, nbA);
    scatter_dual<<<dgrid, HB, 0, s2>>>(pa_row, pa_col, pa_val, pa_ptr, curA, pa_ccol, pa_cval,
                                       ap_row, ap_col, ap_val, ap_ptr, curP, ap_ccol, ap_cval);
    cudaEventRecord(eCsr, s2);

    // ---- main: P-A-P / P-A-P-A-P chains ----
    cudaStreamWaitEvent(0, eCsr, 0);
    spmm_csr_kernel<<<sblocks(N_A), 256>>>(pa_ptr, pa_ccol, pa_cval, bufP,    bufA2,     N_A); // h
    spmm_csr_kernel<<<sblocks(N_P), 256>>>(ap_ptr, ap_ccol, ap_cval, bufA2,   out_pap,   N_P); // pap
    spmm_csr_kernel<<<sblocks(N_A), 256>>>(pa_ptr, pa_ccol, pa_cval, out_pap, bufA2,     N_A); // h2
    spmm_csr_kernel<<<sblocks(N_P), 256>>>(ap_ptr, ap_ccol, ap_cval, bufA2,   out_papap, N_P); // papap

    // ---- s3: A-P-A chain (concurrent with pap chain) ----
    cudaStreamWaitEvent(s3, eCsr, 0);
    spmm_csr_kernel<<<sblocks(N_P), 256, 0, s3>>>(ap_ptr, ap_ccol, ap_cval, bufA1, bufG,    N_P); // g
    spmm_csr_kernel<<<sblocks(N_A), 256, 0, s3>>>(pa_ptr, pa_ccol, pa_cval, bufG,  out_apa, N_A); // apa
    cudaEventRecord(eApa, s3);

    // ---- join ----
    cudaStreamWaitEvent(0, eApa, 0);
}

// round 15
// speedup vs baseline: 1.1779x; 1.1779x over previous
#include <cuda_runtime.h>
#include <cuda_bf16.h>
#include <cstdint>

#define N_P   200000
#define N_A   100000
#define D_MP  64
#define E_NNZ 1200000
#define F_P   256
#define F_A   128

// ===========================================================================
// Static scratch
// ===========================================================================
__device__ __align__(16) float g_bufP [(size_t)N_P * D_MP];   // zp
__device__ __align__(16) float g_bufG [(size_t)N_P * D_MP];   // g (apa chain)
__device__ __align__(16) float g_bufA1[(size_t)N_A * D_MP];   // za
__device__ __align__(16) float g_bufA2[(size_t)N_A * D_MP];   // h, later h2

__device__ __align__(16) uint2 g_WsplitP[(F_P / 32) * 1024];
__device__ __align__(16) uint2 g_WsplitA[(F_A / 32) * 1024];

__device__ int   g_pa_ptr[N_A + 1];
__device__ int   g_ap_ptr[N_P + 1];
__device__ int   g_pa_ccol[E_NNZ];
__device__ float g_pa_cval[E_NNZ];
__device__ int   g_ap_ccol[E_NNZ];
__device__ float g_ap_cval[E_NNZ];
__device__ int   g_cnt[2 * (N_P + N_A)];
__device__ int   g_bsumA[128];
__device__ int   g_bsumP[128];

// ===========================================================================
// bf16 split helpers
// ===========================================================================
__device__ __forceinline__ uint2 split_pack(float a, float b) {
    float fa = __bfloat162float(__float2bfloat16_rn(a));
    float fb = __bfloat162float(__float2bfloat16_rn(b));
    uint32_t hi, lo;
    asm("cvt.rn.bf16x2.f32 %0, %1, %2;" : "=r"(hi) : "f"(fb), "f"(fa));
    asm("cvt.rn.bf16x2.f32 %0, %1, %2;" : "=r"(lo) : "f"(b - fb), "f"(a - fa));
    return make_uint2(hi, lo);
}

__device__ __forceinline__ void mma_bf16(float* d, const uint32_t* a, const uint32_t* b) {
    asm volatile("mma.sync.aligned.m16n8k16.row.col.f32.bf16.bf16.f32 "
                 "{%0,%1,%2,%3}, {%4,%5,%6,%7}, {%8,%9}, {%0,%1,%2,%3};"
                 : "+f"(d[0]), "+f"(d[1]), "+f"(d[2]), "+f"(d[3])
                 : "r"(a[0]), "r"(a[1]), "r"(a[2]), "r"(a[3]),
                   "r"(b[0]), "r"(b[1]));
}

// ===========================================================================
// Prep: split W into chunked smem-image layout
// ===========================================================================
__global__ void prep_W(const float* __restrict__ W, uint2* __restrict__ dst, int F) {
    int i = blockIdx.x * blockDim.x + threadIdx.x;
    int total = (F / 32) * 1024;
    if (i >= total) return;
    int chunk = i >> 10;
    int idx   = i & 1023;
    int nn = idx & 63;
    int kp = idx >> 6;
    int k  = chunk * 32 + kp * 2;
    float w0 = W[(size_t)k * 64 + nn];
    float w1 = W[(size_t)(k + 1) * 64 + nn];
    dst[i] = split_pack(w0, w1);
}

// ===========================================================================
// Tensor-core GEMM (R10/R11 proven config)
// ===========================================================================
template<int F>
__global__ __launch_bounds__(256, 2) void gemm_bf16x3(const float* __restrict__ x,
                                                      const uint2* __restrict__ Wsp,
                                                      float* __restrict__ out, int n) {
    constexpr int NC = F / 32;
    extern __shared__ uint2 smbuf[];
    uint2* wsb[2] = { smbuf,            smbuf + 64 * 20 };
    uint2* xsb[2] = { smbuf + 2 * 64 * 20, smbuf + 2 * 64 * 20 + 128 * 20 };

    const int t    = threadIdx.x;
    const int lane = t & 31;
    const int wid  = t >> 5;
    const int wm   = wid >> 1;
    const int wn   = wid & 1;
    const int tig  = lane & 3;
    const int gid  = lane >> 2;
    const int row0 = blockIdx.x * 128;

    float2 xreg[8];
    uint2  wreg[4];

    auto ldg_chunk = [&](int c) {
        const uint2* src = Wsp + c * 1024;
        #pragma unroll
        for (int j = 0; j < 4; j++) wreg[j] = __ldg(src + j * 256 + t);
        #pragma unroll
        for (int j = 0; j < 8; j++) {
            int idx = j * 256 + t;
            int r   = idx >> 4;
            int kp  = idx & 15;
            int grow = row0 + r;
            xreg[j] = (grow < n)
                ? *(const float2*)(x + (size_t)grow * F + c * 32 + kp * 2)
                : make_float2(0.f, 0.f);
        }
    };
    auto sts_chunk = [&](int b) {
        #pragma unroll
        for (int j = 0; j < 4; j++) {
            int idx = j * 256 + t;
            wsb[b][(idx & 63) * 20 + (idx >> 6)] = wreg[j];
        }
        #pragma unroll
        for (int j = 0; j < 8; j++) {
            int idx = j * 256 + t;
            xsb[b][(idx >> 4) * 20 + (idx & 15)] = split_pack(xreg[j].x, xreg[j].y);
        }
    };

    float acc[2][4][4];
    #pragma unroll
    for (int mt = 0; mt < 2; mt++)
        #pragma unroll
        for (int nt = 0; nt < 4; nt++)
            #pragma unroll
            for (int q = 0; q < 4; q++) acc[mt][nt][q] = 0.f;

    ldg_chunk(0);
    sts_chunk(0);
    if (NC > 1) ldg_chunk(1);
    __syncthreads();

    #pragma unroll
    for (int c = 0; c < NC; c++) {
        if (c + 1 < NC) sts_chunk((c + 1) & 1);
        if (c + 2 < NC) ldg_chunk(c + 2);

        const uint2* xs = xsb[c & 1];
        const uint2* ws = wsb[c & 1];

        #pragma unroll
        for (int ks = 0; ks < 2; ks++) {
            const int p0 = ks * 8 + tig;
            const int p1 = p0 + 4;

            uint32_t ah[2][4], al[2][4];
            #pragma unroll
            for (int mt = 0; mt < 2; mt++) {
                int r0 = wm * 32 + mt * 16 + gid;
                uint2 qa0 = xs[r0 * 20 + p0];
                uint2 qa1 = xs[(r0 + 8) * 20 + p0];
                uint2 qa2 = xs[r0 * 20 + p1];
                uint2 qa3 = xs[(r0 + 8) * 20 + p1];
                ah[mt][0] = qa0.x; ah[mt][1] = qa1.x; ah[mt][2] = qa2.x; ah[mt][3] = qa3.x;
                al[mt][0] = qa0.y; al[mt][1] = qa1.y; al[mt][2] = qa2.y; al[mt][3] = qa3.y;
            }

            #pragma unroll
            for (int nt = 0; nt < 4; nt++) {
                int nn = wn * 32 + nt * 8 + gid;
                uint2 qb0 = ws[nn * 20 + p0];
                uint2 qb1 = ws[nn * 20 + p1];
                uint32_t bh[2] = {qb0.x, qb1.x};
                uint32_t bl[2] = {qb0.y, qb1.y};
                #pragma unroll
                for (int mt = 0; mt < 2; mt++) {
                    mma_bf16(acc[mt][nt], ah[mt], bh);
                    mma_bf16(acc[mt][nt], al[mt], bh);
                    mma_bf16(acc[mt][nt], ah[mt], bl);
                }
            }
        }
        __syncthreads();
    }

    #pragma unroll
    for (int mt = 0; mt < 2; mt++) {
        #pragma unroll
        for (int half = 0; half < 2; half++) {
            int grow = row0 + wm * 32 + mt * 16 + gid + half * 8;
            if (grow < n) {
                float* o = out + (size_t)grow * D_MP + wn * 32 + tig * 2;
                #pragma unroll
                for (int nt = 0; nt < 4; nt++) {
                    float2 v = half ? make_float2(acc[mt][nt][2], acc[mt][nt][3])
                                    : make_float2(acc[mt][nt][0], acc[mt][nt][1]);
                    *(float2*)(o + nt * 8) = v;
                }
            }
        }
    }
}

// ===========================================================================
// CSR build
// ===========================================================================
__global__ void hist_dual(const int* __restrict__ rowA, const int* __restrict__ rowP,
                          int* __restrict__ cntA, int* __restrict__ cntP) {
    int i = blockIdx.x * blockDim.x + threadIdx.x;
    if (i < E_NNZ) {
        atomicAdd(&cntA[rowA[i]], 1);
    } else if (i < 2 * E_NNZ) {
        atomicAdd(&cntP[rowP[i - E_NNZ]], 1);
    }
}

#define SCAN_CHUNK 2048

__global__ void scan_pass1_dual(const int* __restrict__ cntA, int* __restrict__ bsA, int nA,
                                const int* __restrict__ cntP, int* __restrict__ bsP, int nP,
                                int nbA) {
    __shared__ int sh[256];
    const int* cnt = (blockIdx.x < nbA) ? cntA : cntP;
    int*       bs  = (blockIdx.x < nbA) ? bsA  : bsP;
    int        n   = (blockIdx.x < nbA) ? nA   : nP;
    int        blk = (blockIdx.x < nbA) ? blockIdx.x : blockIdx.x - nbA;
    int base = blk * SCAN_CHUNK;
    int t = threadIdx.x;
    int s = 0;
    #pragma unroll
    for (int j = 0; j < 8; j++) {
        int i = base + t * 8 + j;
        if (i < n) s += cnt[i];
    }
    sh[t] = s;
    __syncthreads();
    for (int off = 128; off > 0; off >>= 1) {
        if (t < off) sh[t] += sh[t + off];
        __syncthreads();
    }
    if (t == 0) bs[blk] = sh[0];
}

__global__ void scan_pass2_dual(int* __restrict__ bsA, int nbA,
                                int* __restrict__ bsP, int nbP) {
    __shared__ int sh[128];
    int* bs = blockIdx.x ? bsP : bsA;
    int nb  = blockIdx.x ? nbP : nbA;
    int t = threadIdx.x;
    int v = (t < nb) ? bs[t] : 0;
    sh[t] = v;
    __syncthreads();
    for (int off = 1; off < 128; off <<= 1) {
        int xx = (t >= off) ? sh[t - off] : 0;
        __syncthreads();
        sh[t] += xx;
        __syncthreads();
    }
    if (t < nb) bs[t] = sh[t] - v;
}

__global__ void scan_pass3_dual(const int* __restrict__ cntA, const int* __restrict__ bsA,
                                int* __restrict__ ptrA, int nA,
                                const int* __restrict__ cntP, const int* __restrict__ bsP,
                                int* __restrict__ ptrP, int nP, int nbA) {
    __shared__ int sh[256];
    const int* cnt = (blockIdx.x < nbA) ? cntA : cntP;
    const int* bs  = (blockIdx.x < nbA) ? bsA  : bsP;
    int*       ptr = (blockIdx.x < nbA) ? ptrA : ptrP;
    int        n   = (blockIdx.x < nbA) ? nA   : nP;
    int        blk = (blockIdx.x < nbA) ? blockIdx.x : blockIdx.x - nbA;
    int base = blk * SCAN_CHUNK;
    int t = threadIdx.x;
    int v[8];
    int s = 0;
    #pragma unroll
    for (int j = 0; j < 8; j++) {
        int i = base + t * 8 + j;
        v[j] = (i < n) ? cnt[i] : 0;
        s += v[j];
    }
    sh[t] = s;
    __syncthreads();
    for (int off = 1; off < 256; off <<= 1) {
        int xx = (t >= off) ? sh[t - off] : 0;
        __syncthreads();
        sh[t] += xx;
        __syncthreads();
    }
    int ex = sh[t] - s + bs[blk];
    #pragma unroll
    for (int j = 0; j < 8; j++) {
        int i = base + t * 8 + j;
        if (i < n) {
            ptr[i] = ex;
            ex += v[j];
            if (i == n - 1) ptr[n] = ex;
        }
    }
}

__global__ void scatter_dual(const int* __restrict__ rowA, const int* __restrict__ colA,
                             const float* __restrict__ valA,
                             const int* __restrict__ ptrA, int* __restrict__ curA,
                             int* __restrict__ ccolA, float* __restrict__ cvalA,
                             const int* __restrict__ rowP, const int* __restrict__ colP,
                             const float* __restrict__ valP,
                             const int* __restrict__ ptrP, int* __restrict__ curP,
                             int* __restrict__ ccolP, float* __restrict__ cvalP) {
    int i = blockIdx.x * blockDim.x + threadIdx.x;
    if (i < E_NNZ) {
        int r = rowA[i];
        int p = ptrA[r] + atomicAdd(&curA[r], 1);
        ccolA[p] = colA[i];
        cvalA[p] = valA[i];
    } else if (i < 2 * E_NNZ) {
        int j = i - E_NNZ;
        int r = rowP[j];
        int p = ptrP[r] + atomicAdd(&curP[r], 1);
        ccolP[p] = colP[j];
        cvalP[p] = valP[j];
    }
}

// ===========================================================================
// CSR SpMM (R11 proven shape) with row-range [rbeg, rend)
// ===========================================================================
__global__ void spmm_csr_kernel(const int* __restrict__ ptr,
                                const int* __restrict__ ccol,
                                const float* __restrict__ cval,
                                const float* __restrict__ z,
                                float* __restrict__ out, int rbeg, int rend) {
    int w = rbeg + ((blockIdx.x * blockDim.x + threadIdx.x) >> 5);
    if (w >= rend) return;
    int lane = threadIdx.x & 31;
    int half = lane >> 4;
    int s    = lane & 15;

    int beg = ptr[w], end = ptr[w + 1];
    float4 acc0 = make_float4(0.f, 0.f, 0.f, 0.f);
    float4 acc1 = make_float4(0.f, 0.f, 0.f, 0.f);

    int e = beg + half;
    for (; e + 2 < end; e += 4) {
        int   c0 = __ldg(ccol + e);
        float v0 = __ldg(cval + e);
        int   c1 = __ldg(ccol + e + 2);
        float v1 = __ldg(cval + e + 2);
        float4 z0 = __ldg((const float4*)(z + (size_t)c0 * D_MP) + s);
        float4 z1 = __ldg((const float4*)(z + (size_t)c1 * D_MP) + s);
        acc0.x = fmaf(v0, z0.x, acc0.x);
        acc0.y = fmaf(v0, z0.y, acc0.y);
        acc0.z = fmaf(v0, z0.z, acc0.z);
        acc0.w = fmaf(v0, z0.w, acc0.w);
        acc1.x = fmaf(v1, z1.x, acc1.x);
        acc1.y = fmaf(v1, z1.y, acc1.y);
        acc1.z = fmaf(v1, z1.z, acc1.z);
        acc1.w = fmaf(v1, z1.w, acc1.w);
    }
    if (e < end) {
        int   c = __ldg(ccol + e);
        float v = __ldg(cval + e);
        float4 zv = __ldg((const float4*)(z + (size_t)c * D_MP) + s);
        acc0.x = fmaf(v, zv.x, acc0.x);
        acc0.y = fmaf(v, zv.y, acc0.y);
        acc0.z = fmaf(v, zv.z, acc0.z);
        acc0.w = fmaf(v, zv.w, acc0.w);
    }
    acc0.x += acc1.x; acc0.y += acc1.y; acc0.z += acc1.z; acc0.w += acc1.w;

    acc0.x += __shfl_xor_sync(0xffffffffu, acc0.x, 16);
    acc0.y += __shfl_xor_sync(0xffffffffu, acc0.y, 16);
    acc0.z += __shfl_xor_sync(0xffffffffu, acc0.z, 16);
    acc0.w += __shfl_xor_sync(0xffffffffu, acc0.w, 16);
    if (half == 0)
        *((float4*)(out + (size_t)w * D_MP) + s) = acc0;
}

// ===========================================================================
// Launch — R11 schedule + tail-splitting: h2 and papap run as half-row
// grids on BOTH streams (s3 is idle in that window under R11).
// ===========================================================================
extern "C" void kernel_launch(void* const* d_in, const int* in_sizes, int n_in,
                              void* d_out, int out_size) {
    const float* x_paper  = (const float*)d_in[0];
    const float* x_author = (const float*)d_in[1];
    const float* W_paper  = (const float*)d_in[2];
    const float* W_author = (const float*)d_in[3];
    const int*   pa_row   = (const int*)  d_in[4];
    const int*   pa_col   = (const int*)  d_in[5];
    const float* pa_val   = (const float*)d_in[6];
    const int*   ap_row   = (const int*)  d_in[7];
    const int*   ap_col   = (const int*)  d_in[8];
    const float* ap_val   = (const float*)d_in[9];

    float* out       = (float*)d_out;
    float* out_pap   = out;
    float* out_papap = out + (size_t)N_P * D_MP;
    float* out_apa   = out + (size_t)2 * N_P * D_MP;

    float *bufP, *bufG, *bufA1, *bufA2;
    uint2 *WspP, *WspA;
    int *pa_ptr, *ap_ptr, *pa_ccol, *ap_ccol, *cnt, *bsumA, *bsumP;
    float *pa_cval, *ap_cval;
    cudaGetSymbolAddress((void**)&bufP,    g_bufP);
    cudaGetSymbolAddress((void**)&bufG,    g_bufG);
    cudaGetSymbolAddress((void**)&bufA1,   g_bufA1);
    cudaGetSymbolAddress((void**)&bufA2,   g_bufA2);
    cudaGetSymbolAddress((void**)&WspP,    g_WsplitP);
    cudaGetSymbolAddress((void**)&WspA,    g_WsplitA);
    cudaGetSymbolAddress((void**)&pa_ptr,  g_pa_ptr);
    cudaGetSymbolAddress((void**)&ap_ptr,  g_ap_ptr);
    cudaGetSymbolAddress((void**)&pa_ccol, g_pa_ccol);
    cudaGetSymbolAddress((void**)&pa_cval, g_pa_cval);
    cudaGetSymbolAddress((void**)&ap_ccol, g_ap_ccol);
    cudaGetSymbolAddress((void**)&ap_cval, g_ap_cval);
    cudaGetSymbolAddress((void**)&cnt,     g_cnt);
    cudaGetSymbolAddress((void**)&bsumA,   g_bsumA);
    cudaGetSymbolAddress((void**)&bsumP,   g_bsumP);

    int* cntA = cnt;
    int* curA = cnt + N_A;
    int* cntP = cnt + 2 * N_A;
    int* curP = cnt + 2 * N_A + N_P;

    static cudaStream_t s2 = nullptr, s3 = nullptr;
    static cudaEvent_t eFork, eCsr, ePrep, ePap, eH2a, eH2b, eEnd;
    if (s2 == nullptr) {
        cudaStreamCreateWithFlags(&s2, cudaStreamNonBlocking);
        cudaStreamCreateWithFlags(&s3, cudaStreamNonBlocking);
        cudaEventCreateWithFlags(&eFork, cudaEventDisableTiming);
        cudaEventCreateWithFlags(&eCsr,  cudaEventDisableTiming);
        cudaEventCreateWithFlags(&ePrep, cudaEventDisableTiming);
        cudaEventCreateWithFlags(&ePap,  cudaEventDisableTiming);
        cudaEventCreateWithFlags(&eH2a,  cudaEventDisableTiming);
        cudaEventCreateWithFlags(&eH2b,  cudaEventDisableTiming);
        cudaEventCreateWithFlags(&eEnd,  cudaEventDisableTiming);
    }

    const int GEMM_SMEM = (2 * 64 * 20 + 2 * 128 * 20) * (int)sizeof(uint2);  // 61440
    cudaFuncSetAttribute(gemm_bf16x3<F_P>, cudaFuncAttributeMaxDynamicSharedMemorySize, GEMM_SMEM);
    cudaFuncSetAttribute(gemm_bf16x3<F_A>, cudaFuncAttributeMaxDynamicSharedMemorySize, GEMM_SMEM);

    const int HB = 256;
    const int dgrid = (2 * E_NNZ + HB - 1) / HB;
    const int nbA = (N_A + SCAN_CHUNK - 1) / SCAN_CHUNK;
    const int nbP = (N_P + SCAN_CHUNK - 1) / SCAN_CHUNK;
    auto sgrid = [](int nrows) { return (nrows * 32 + 255) / 256; };

    const int NA_H = N_A / 2;
    const int NP_H = N_P / 2;

    // ---- fork ----
    cudaEventRecord(eFork, 0);
    cudaStreamWaitEvent(s2, eFork, 0);
    cudaStreamWaitEvent(s3, eFork, 0);

    // ---- s2: CSR build (hidden under GEMMs) ----
    cudaMemsetAsync(cnt, 0, (size_t)2 * (N_P + N_A) * sizeof(int), s2);

    // main: W prep
    prep_W<<<(F_P / 32 * 1024 + 255) / 256, 256>>>(W_paper,  WspP, F_P);
    prep_W<<<(F_A / 32 * 1024 + 255) / 256, 256>>>(W_author, WspA, F_A);
    cudaEventRecord(ePrep, 0);
    cudaStreamWaitEvent(s3, ePrep, 0);

    // s2: hist
    hist_dual<<<dgrid, HB, 0, s2>>>(pa_row, ap_row, cntA, cntP);

    // main: gemm P (ncu capture slot 3); s3: gemm A concurrent (R11 cfg)
    gemm_bf16x3<F_P><<<(N_P + 127) / 128, 256, GEMM_SMEM>>>(x_paper, WspP, bufP, N_P);
    gemm_bf16x3<F_A><<<(N_A + 127) / 128, 256, GEMM_SMEM, s3>>>(x_author, WspA, bufA1, N_A);

    // s2: rest of CSR build
    scan_pass1_dual<<<nbA + nbP, 256, 0, s2>>>(cntA, bsumA, N_A, cntP, bsumP, N_P, nbA);
    scan_pass2_dual<<<2, 128, 0, s2>>>(bsumA, nbA, bsumP, nbP);
    scan_pass3_dual<<<nbA + nbP, 256, 0, s2>>>(cntA, bsumA, pa_ptr, N_A,
                                               cntP, bsumP, ap_ptr, N_P, nbA);
    scatter_dual<<<dgrid, HB, 0, s2>>>(pa_row, pa_col, pa_val, pa_ptr, curA, pa_ccol, pa_cval,
                                       ap_row, ap_col, ap_val, ap_ptr, curP, ap_ccol, ap_cval);
    cudaEventRecord(eCsr, s2);

    // ---- main: h -> pap ----
    cudaStreamWaitEvent(0, eCsr, 0);
    spmm_csr_kernel<<<sgrid(N_A), 256>>>(pa_ptr, pa_ccol, pa_cval, bufP,  bufA2,   0, N_A); // h
    spmm_csr_kernel<<<sgrid(N_P), 256>>>(ap_ptr, ap_ccol, ap_cval, bufA2, out_pap, 0, N_P); // pap
    cudaEventRecord(ePap, 0);

    // ---- s3: g -> apa (concurrent with h/pap) ----
    cudaStreamWaitEvent(s3, eCsr, 0);
    spmm_csr_kernel<<<sgrid(N_P), 256, 0, s3>>>(ap_ptr, ap_ccol, ap_cval, bufA1, bufG,    0, N_P); // g
    spmm_csr_kernel<<<sgrid(N_A), 256, 0, s3>>>(pa_ptr, pa_ccol, pa_cval, bufG,  out_apa, 0, N_A); // apa

    // ---- h2 = pa @ pap : split across main (lo) + s3 (hi) ----
    cudaStreamWaitEvent(s3, ePap, 0);
    spmm_csr_kernel<<<sgrid(NA_H),       256       >>>(pa_ptr, pa_ccol, pa_cval, out_pap, bufA2, 0,    NA_H); // lo
    spmm_csr_kernel<<<sgrid(N_A - NA_H), 256, 0, s3>>>(pa_ptr, pa_ccol, pa_cval, out_pap, bufA2, NA_H, N_A);  // hi
    cudaEventRecord(eH2a, 0);
    cudaEventRecord(eH2b, s3);

    // ---- papap = ap @ h2 : both halves need BOTH h2 halves ----
    cudaStreamWaitEvent(0,  eH2b, 0);
    cudaStreamWaitEvent(s3, eH2a, 0);
    spmm_csr_kernel<<<sgrid(NP_H),       256       >>>(ap_ptr, ap_ccol, ap_cval, bufA2, out_papap, 0,    NP_H); // lo
    spmm_csr_kernel<<<sgrid(N_P - NP_H), 256, 0, s3>>>(ap_ptr, ap_ccol, ap_cval, bufA2, out_papap, NP_H, N_P);  // hi
    cudaEventRecord(eEnd, s3);

    // ---- join ----
    cudaStreamWaitEvent(0, eEnd, 0);
}

// round 16
// speedup vs baseline: 1.2380x; 1.0510x over previous
#include <cuda_runtime.h>
#include <cuda_bf16.h>
#include <cuda_fp16.h>
#include <cstdint>

#define N_P   200000
#define N_A   100000
#define D_MP  64
#define E_NNZ 1200000
#define F_P   256
#define F_A   128

// ===========================================================================
// Static scratch (fp16 operand matrices for SpMM gathers)
// ===========================================================================
__device__ __align__(16) __half g_zpH [(size_t)N_P * D_MP];  // zp  (gemm P out)
__device__ __align__(16) __half g_zaH [(size_t)N_A * D_MP];  // za  (gemm A out)
__device__ __align__(16) __half g_hH  [(size_t)N_A * D_MP];  // h, then h2
__device__ __align__(16) __half g_papH[(size_t)N_P * D_MP];  // pap fp16 copy
__device__ __align__(16) __half g_gH  [(size_t)N_P * D_MP];  // g

__device__ __align__(16) uint2 g_WsplitP[(F_P / 32) * 1024];
__device__ __align__(16) uint2 g_WsplitA[(F_A / 32) * 1024];

__device__ int   g_pa_ptr[N_A + 1];
__device__ int   g_ap_ptr[N_P + 1];
__device__ int   g_pa_ccol[E_NNZ];
__device__ float g_pa_cval[E_NNZ];
__device__ int   g_ap_ccol[E_NNZ];
__device__ float g_ap_cval[E_NNZ];
__device__ int   g_cnt[2 * (N_P + N_A)];
__device__ int   g_bsumA[128];
__device__ int   g_bsumP[128];

// ===========================================================================
// bf16 split helpers (GEMM)
// ===========================================================================
__device__ __forceinline__ uint2 split_pack(float a, float b) {
    float fa = __bfloat162float(__float2bfloat16_rn(a));
    float fb = __bfloat162float(__float2bfloat16_rn(b));
    uint32_t hi, lo;
    asm("cvt.rn.bf16x2.f32 %0, %1, %2;" : "=r"(hi) : "f"(fb), "f"(fa));
    asm("cvt.rn.bf16x2.f32 %0, %1, %2;" : "=r"(lo) : "f"(b - fb), "f"(a - fa));
    return make_uint2(hi, lo);
}

__device__ __forceinline__ void mma_bf16(float* d, const uint32_t* a, const uint32_t* b) {
    asm volatile("mma.sync.aligned.m16n8k16.row.col.f32.bf16.bf16.f32 "
                 "{%0,%1,%2,%3}, {%4,%5,%6,%7}, {%8,%9}, {%0,%1,%2,%3};"
                 : "+f"(d[0]), "+f"(d[1]), "+f"(d[2]), "+f"(d[3])
                 : "r"(a[0]), "r"(a[1]), "r"(a[2]), "r"(a[3]),
                   "r"(b[0]), "r"(b[1]));
}

// ===========================================================================
// Prep: split W into chunked smem-image layout
// ===========================================================================
__global__ void prep_W(const float* __restrict__ W, uint2* __restrict__ dst, int F) {
    int i = blockIdx.x * blockDim.x + threadIdx.x;
    int total = (F / 32) * 1024;
    if (i >= total) return;
    int chunk = i >> 10;
    int idx   = i & 1023;
    int nn = idx & 63;
    int kp = idx >> 6;
    int k  = chunk * 32 + kp * 2;
    float w0 = W[(size_t)k * 64 + nn];
    float w1 = W[(size_t)(k + 1) * 64 + nn];
    dst[i] = split_pack(w0, w1);
}

// ===========================================================================
// Tensor-core GEMM (R10/R11 proven config), fp16 output
// ===========================================================================
template<int F>
__global__ __launch_bounds__(256, 2) void gemm_bf16x3(const float* __restrict__ x,
                                                      const uint2* __restrict__ Wsp,
                                                      __half* __restrict__ out, int n) {
    constexpr int NC = F / 32;
    extern __shared__ uint2 smbuf[];
    uint2* wsb[2] = { smbuf,            smbuf + 64 * 20 };
    uint2* xsb[2] = { smbuf + 2 * 64 * 20, smbuf + 2 * 64 * 20 + 128 * 20 };

    const int t    = threadIdx.x;
    const int lane = t & 31;
    const int wid  = t >> 5;
    const int wm   = wid >> 1;
    const int wn   = wid & 1;
    const int tig  = lane & 3;
    const int gid  = lane >> 2;
    const int row0 = blockIdx.x * 128;

    float2 xreg[8];
    uint2  wreg[4];

    auto ldg_chunk = [&](int c) {
        const uint2* src = Wsp + c * 1024;
        #pragma unroll
        for (int j = 0; j < 4; j++) wreg[j] = __ldg(src + j * 256 + t);
        #pragma unroll
        for (int j = 0; j < 8; j++) {
            int idx = j * 256 + t;
            int r   = idx >> 4;
            int kp  = idx & 15;
            int grow = row0 + r;
            xreg[j] = (grow < n)
                ? *(const float2*)(x + (size_t)grow * F + c * 32 + kp * 2)
                : make_float2(0.f, 0.f);
        }
    };
    auto sts_chunk = [&](int b) {
        #pragma unroll
        for (int j = 0; j < 4; j++) {
            int idx = j * 256 + t;
            wsb[b][(idx & 63) * 20 + (idx >> 6)] = wreg[j];
        }
        #pragma unroll
        for (int j = 0; j < 8; j++) {
            int idx = j * 256 + t;
            xsb[b][(idx >> 4) * 20 + (idx & 15)] = split_pack(xreg[j].x, xreg[j].y);
        }
    };

    float acc[2][4][4];
    #pragma unroll
    for (int mt = 0; mt < 2; mt++)
        #pragma unroll
        for (int nt = 0; nt < 4; nt++)
            #pragma unroll
            for (int q = 0; q < 4; q++) acc[mt][nt][q] = 0.f;

    ldg_chunk(0);
    sts_chunk(0);
    if (NC > 1) ldg_chunk(1);
    __syncthreads();

    #pragma unroll
    for (int c = 0; c < NC; c++) {
        if (c + 1 < NC) sts_chunk((c + 1) & 1);
        if (c + 2 < NC) ldg_chunk(c + 2);

        const uint2* xs = xsb[c & 1];
        const uint2* ws = wsb[c & 1];

        #pragma unroll
        for (int ks = 0; ks < 2; ks++) {
            const int p0 = ks * 8 + tig;
            const int p1 = p0 + 4;

            uint32_t ah[2][4], al[2][4];
            #pragma unroll
            for (int mt = 0; mt < 2; mt++) {
                int r0 = wm * 32 + mt * 16 + gid;
                uint2 qa0 = xs[r0 * 20 + p0];
                uint2 qa1 = xs[(r0 + 8) * 20 + p0];
                uint2 qa2 = xs[r0 * 20 + p1];
                uint2 qa3 = xs[(r0 + 8) * 20 + p1];
                ah[mt][0] = qa0.x; ah[mt][1] = qa1.x; ah[mt][2] = qa2.x; ah[mt][3] = qa3.x;
                al[mt][0] = qa0.y; al[mt][1] = qa1.y; al[mt][2] = qa2.y; al[mt][3] = qa3.y;
            }

            #pragma unroll
            for (int nt = 0; nt < 4; nt++) {
                int nn = wn * 32 + nt * 8 + gid;
                uint2 qb0 = ws[nn * 20 + p0];
                uint2 qb1 = ws[nn * 20 + p1];
                uint32_t bh[2] = {qb0.x, qb1.x};
                uint32_t bl[2] = {qb0.y, qb1.y};
                #pragma unroll
                for (int mt = 0; mt < 2; mt++) {
                    mma_bf16(acc[mt][nt], ah[mt], bh);
                    mma_bf16(acc[mt][nt], al[mt], bh);
                    mma_bf16(acc[mt][nt], ah[mt], bl);
                }
            }
        }
        __syncthreads();
    }

    #pragma unroll
    for (int mt = 0; mt < 2; mt++) {
        #pragma unroll
        for (int half = 0; half < 2; half++) {
            int grow = row0 + wm * 32 + mt * 16 + gid + half * 8;
            if (grow < n) {
                __half* o = out + (size_t)grow * D_MP + wn * 32 + tig * 2;
                #pragma unroll
                for (int nt = 0; nt < 4; nt++) {
                    float2 v = half ? make_float2(acc[mt][nt][2], acc[mt][nt][3])
                                    : make_float2(acc[mt][nt][0], acc[mt][nt][1]);
                    *(__half2*)(o + nt * 8) = __floats2half2_rn(v.x, v.y);
                }
            }
        }
    }
}

// ===========================================================================
// CSR build
// ===========================================================================
__global__ void hist_dual(const int* __restrict__ rowA, const int* __restrict__ rowP,
                          int* __restrict__ cntA, int* __restrict__ cntP) {
    int i = blockIdx.x * blockDim.x + threadIdx.x;
    if (i < E_NNZ) {
        atomicAdd(&cntA[rowA[i]], 1);
    } else if (i < 2 * E_NNZ) {
        atomicAdd(&cntP[rowP[i - E_NNZ]], 1);
    }
}

#define SCAN_CHUNK 2048

__global__ void scan_pass1_dual(const int* __restrict__ cntA, int* __restrict__ bsA, int nA,
                                const int* __restrict__ cntP, int* __restrict__ bsP, int nP,
                                int nbA) {
    __shared__ int sh[256];
    const int* cnt = (blockIdx.x < nbA) ? cntA : cntP;
    int*       bs  = (blockIdx.x < nbA) ? bsA  : bsP;
    int        n   = (blockIdx.x < nbA) ? nA   : nP;
    int        blk = (blockIdx.x < nbA) ? blockIdx.x : blockIdx.x - nbA;
    int base = blk * SCAN_CHUNK;
    int t = threadIdx.x;
    int s = 0;
    #pragma unroll
    for (int j = 0; j < 8; j++) {
        int i = base + t * 8 + j;
        if (i < n) s += cnt[i];
    }
    sh[t] = s;
    __syncthreads();
    for (int off = 128; off > 0; off >>= 1) {
        if (t < off) sh[t] += sh[t + off];
        __syncthreads();
    }
    if (t == 0) bs[blk] = sh[0];
}

__global__ void scan_pass2_dual(int* __restrict__ bsA, int nbA,
                                int* __restrict__ bsP, int nbP) {
    __shared__ int sh[128];
    int* bs = blockIdx.x ? bsP : bsA;
    int nb  = blockIdx.x ? nbP : nbA;
    int t = threadIdx.x;
    int v = (t < nb) ? bs[t] : 0;
    sh[t] = v;
    __syncthreads();
    for (int off = 1; off < 128; off <<= 1) {
        int xx = (t >= off) ? sh[t - off] : 0;
        __syncthreads();
        sh[t] += xx;
        __syncthreads();
    }
    if (t < nb) bs[t] = sh[t] - v;
}

__global__ void scan_pass3_dual(const int* __restrict__ cntA, const int* __restrict__ bsA,
                                int* __restrict__ ptrA, int nA,
                                const int* __restrict__ cntP, const int* __restrict__ bsP,
                                int* __restrict__ ptrP, int nP, int nbA) {
    __shared__ int sh[256];
    const int* cnt = (blockIdx.x < nbA) ? cntA : cntP;
    const int* bs  = (blockIdx.x < nbA) ? bsA  : bsP;
    int*       ptr = (blockIdx.x < nbA) ? ptrA : ptrP;
    int        n   = (blockIdx.x < nbA) ? nA   : nP;
    int        blk = (blockIdx.x < nbA) ? blockIdx.x : blockIdx.x - nbA;
    int base = blk * SCAN_CHUNK;
    int t = threadIdx.x;
    int v[8];
    int s = 0;
    #pragma unroll
    for (int j = 0; j < 8; j++) {
        int i = base + t * 8 + j;
        v[j] = (i < n) ? cnt[i] : 0;
        s += v[j];
    }
    sh[t] = s;
    __syncthreads();
    for (int off = 1; off < 256; off <<= 1) {
        int xx = (t >= off) ? sh[t - off] : 0;
        __syncthreads();
        sh[t] += xx;
        __syncthreads();
    }
    int ex = sh[t] - s + bs[blk];
    #pragma unroll
    for (int j = 0; j < 8; j++) {
        int i = base + t * 8 + j;
        if (i < n) {
            ptr[i] = ex;
            ex += v[j];
            if (i == n - 1) ptr[n] = ex;
        }
    }
}

__global__ void scatter_dual(const int* __restrict__ rowA, const int* __restrict__ colA,
                             const float* __restrict__ valA,
                             const int* __restrict__ ptrA, int* __restrict__ curA,
                             int* __restrict__ ccolA, float* __restrict__ cvalA,
                             const int* __restrict__ rowP, const int* __restrict__ colP,
                             const float* __restrict__ valP,
                             const int* __restrict__ ptrP, int* __restrict__ curP,
                             int* __restrict__ ccolP, float* __restrict__ cvalP) {
    int i = blockIdx.x * blockDim.x + threadIdx.x;
    if (i < E_NNZ) {
        int r = rowA[i];
        int p = ptrA[r] + atomicAdd(&curA[r], 1);
        ccolA[p] = colA[i];
        cvalA[p] = valA[i];
    } else if (i < 2 * E_NNZ) {
        int j = i - E_NNZ;
        int r = rowP[j];
        int p = ptrP[r] + atomicAdd(&curP[r], 1);
        ccolP[p] = colP[j];
        cvalP[p] = valP[j];
    }
}

// ===========================================================================
// CSR SpMM, fp16 gather source (128B per edge vs 256B fp32).
// R11-proven structure: warp per row, 2x16-lane halves, 2-edge unroll.
// Lane s covers cols 4s..4s+3 (uint2 = 4 halves).
// Outputs: optional fp32 (outF) and/or fp16 (outH).
// ===========================================================================
__global__ void spmm_csr_h(const int* __restrict__ ptr,
                           const int* __restrict__ ccol,
                           const float* __restrict__ cval,
                           const __half* __restrict__ z,
                           float* __restrict__ outF,
                           __half* __restrict__ outH, int nrows) {
    int w = (blockIdx.x * blockDim.x + threadIdx.x) >> 5;
    if (w >= nrows) return;
    int lane = threadIdx.x & 31;
    int half = lane >> 4;
    int s    = lane & 15;

    int beg = ptr[w], end = ptr[w + 1];
    float4 acc0 = make_float4(0.f, 0.f, 0.f, 0.f);
    float4 acc1 = make_float4(0.f, 0.f, 0.f, 0.f);

    int e = beg + half;
    for (; e + 2 < end; e += 4) {
        int   c0 = __ldg(ccol + e);
        float v0 = __ldg(cval + e);
        int   c1 = __ldg(ccol + e + 2);
        float v1 = __ldg(cval + e + 2);
        uint2 q0 = __ldg((const uint2*)(z + (size_t)c0 * D_MP) + s);
        uint2 q1 = __ldg((const uint2*)(z + (size_t)c1 * D_MP) + s);
        float2 a0 = __half22float2(*(__half2*)&q0.x);
        float2 b0 = __half22float2(*(__half2*)&q0.y);
        float2 a1 = __half22float2(*(__half2*)&q1.x);
        float2 b1 = __half22float2(*(__half2*)&q1.y);
        acc0.x = fmaf(v0, a0.x, acc0.x);
        acc0.y = fmaf(v0, a0.y, acc0.y);
        acc0.z = fmaf(v0, b0.x, acc0.z);
        acc0.w = fmaf(v0, b0.y, acc0.w);
        acc1.x = fmaf(v1, a1.x, acc1.x);
        acc1.y = fmaf(v1, a1.y, acc1.y);
        acc1.z = fmaf(v1, b1.x, acc1.z);
        acc1.w = fmaf(v1, b1.y, acc1.w);
    }
    if (e < end) {
        int   c = __ldg(ccol + e);
        float v = __ldg(cval + e);
        uint2 q = __ldg((const uint2*)(z + (size_t)c * D_MP) + s);
        float2 a = __half22float2(*(__half2*)&q.x);
        float2 b = __half22float2(*(__half2*)&q.y);
        acc0.x = fmaf(v, a.x, acc0.x);
        acc0.y = fmaf(v, a.y, acc0.y);
        acc0.z = fmaf(v, b.x, acc0.z);
        acc0.w = fmaf(v, b.y, acc0.w);
    }
    acc0.x += acc1.x; acc0.y += acc1.y; acc0.z += acc1.z; acc0.w += acc1.w;

    acc0.x += __shfl_xor_sync(0xffffffffu, acc0.x, 16);
    acc0.y += __shfl_xor_sync(0xffffffffu, acc0.y, 16);
    acc0.z += __shfl_xor_sync(0xffffffffu, acc0.z, 16);
    acc0.w += __shfl_xor_sync(0xffffffffu, acc0.w, 16);
    if (half == 0) {
        if (outF)
            *((float4*)(outF + (size_t)w * D_MP) + s) = acc0;
        if (outH) {
            uint2 q;
            *(__half2*)&q.x = __floats2half2_rn(acc0.x, acc0.y);
            *(__half2*)&q.y = __floats2half2_rn(acc0.z, acc0.w);
            *((uint2*)(outH + (size_t)w * D_MP) + s) = q;
        }
    }
}

// ===========================================================================
// Launch — exact R11 schedule, fp16 SpMM operands
// ===========================================================================
extern "C" void kernel_launch(void* const* d_in, const int* in_sizes, int n_in,
                              void* d_out, int out_size) {
    const float* x_paper  = (const float*)d_in[0];
    const float* x_author = (const float*)d_in[1];
    const float* W_paper  = (const float*)d_in[2];
    const float* W_author = (const float*)d_in[3];
    const int*   pa_row   = (const int*)  d_in[4];
    const int*   pa_col   = (const int*)  d_in[5];
    const float* pa_val   = (const float*)d_in[6];
    const int*   ap_row   = (const int*)  d_in[7];
    const int*   ap_col   = (const int*)  d_in[8];
    const float* ap_val   = (const float*)d_in[9];

    float* out       = (float*)d_out;
    float* out_pap   = out;
    float* out_papap = out + (size_t)N_P * D_MP;
    float* out_apa   = out + (size_t)2 * N_P * D_MP;

    __half *zpH, *zaH, *hH, *papH, *gH;
    uint2 *WspP, *WspA;
    int *pa_ptr, *ap_ptr, *pa_ccol, *ap_ccol, *cnt, *bsumA, *bsumP;
    float *pa_cval, *ap_cval;
    cudaGetSymbolAddress((void**)&zpH,     g_zpH);
    cudaGetSymbolAddress((void**)&zaH,     g_zaH);
    cudaGetSymbolAddress((void**)&hH,      g_hH);
    cudaGetSymbolAddress((void**)&papH,    g_papH);
    cudaGetSymbolAddress((void**)&gH,      g_gH);
    cudaGetSymbolAddress((void**)&WspP,    g_WsplitP);
    cudaGetSymbolAddress((void**)&WspA,    g_WsplitA);
    cudaGetSymbolAddress((void**)&pa_ptr,  g_pa_ptr);
    cudaGetSymbolAddress((void**)&ap_ptr,  g_ap_ptr);
    cudaGetSymbolAddress((void**)&pa_ccol, g_pa_ccol);
    cudaGetSymbolAddress((void**)&pa_cval, g_pa_cval);
    cudaGetSymbolAddress((void**)&ap_ccol, g_ap_ccol);
    cudaGetSymbolAddress((void**)&ap_cval, g_ap_cval);
    cudaGetSymbolAddress((void**)&cnt,     g_cnt);
    cudaGetSymbolAddress((void**)&bsumA,   g_bsumA);
    cudaGetSymbolAddress((void**)&bsumP,   g_bsumP);

    int* cntA = cnt;
    int* curA = cnt + N_A;
    int* cntP = cnt + 2 * N_A;
    int* curP = cnt + 2 * N_A + N_P;

    static cudaStream_t s2 = nullptr, s3 = nullptr;
    static cudaEvent_t eFork, eCsr, ePrep, eApa;
    if (s2 == nullptr) {
        cudaStreamCreateWithFlags(&s2, cudaStreamNonBlocking);
        cudaStreamCreateWithFlags(&s3, cudaStreamNonBlocking);
        cudaEventCreateWithFlags(&eFork, cudaEventDisableTiming);
        cudaEventCreateWithFlags(&eCsr,  cudaEventDisableTiming);
        cudaEventCreateWithFlags(&ePrep, cudaEventDisableTiming);
        cudaEventCreateWithFlags(&eApa,  cudaEventDisableTiming);
    }

    const int GEMM_SMEM = (2 * 64 * 20 + 2 * 128 * 20) * (int)sizeof(uint2);  // 61440
    cudaFuncSetAttribute(gemm_bf16x3<F_P>, cudaFuncAttributeMaxDynamicSharedMemorySize, GEMM_SMEM);
    cudaFuncSetAttribute(gemm_bf16x3<F_A>, cudaFuncAttributeMaxDynamicSharedMemorySize, GEMM_SMEM);

    const int HB = 256;
    const int dgrid = (2 * E_NNZ + HB - 1) / HB;
    const int nbA = (N_A + SCAN_CHUNK - 1) / SCAN_CHUNK;
    const int nbP = (N_P + SCAN_CHUNK - 1) / SCAN_CHUNK;
    auto sgrid = [](int nrows) { return (nrows * 32 + 255) / 256; };

    // ---- fork ----
    cudaEventRecord(eFork, 0);
    cudaStreamWaitEvent(s2, eFork, 0);
    cudaStreamWaitEvent(s3, eFork, 0);

    // ---- s2: CSR build (hidden under GEMMs) ----
    cudaMemsetAsync(cnt, 0, (size_t)2 * (N_P + N_A) * sizeof(int), s2);

    // main: W prep
    prep_W<<<(F_P / 32 * 1024 + 255) / 256, 256>>>(W_paper,  WspP, F_P);
    prep_W<<<(F_A / 32 * 1024 + 255) / 256, 256>>>(W_author, WspA, F_A);
    cudaEventRecord(ePrep, 0);
    cudaStreamWaitEvent(s3, ePrep, 0);

    // s2: hist
    hist_dual<<<dgrid, HB, 0, s2>>>(pa_row, ap_row, cntA, cntP);

    // main: gemm P (ncu capture slot 3); s3: gemm A concurrent
    gemm_bf16x3<F_P><<<(N_P + 127) / 128, 256, GEMM_SMEM>>>(x_paper, WspP, zpH, N_P);
    gemm_bf16x3<F_A><<<(N_A + 127) / 128, 256, GEMM_SMEM, s3>>>(x_author, WspA, zaH, N_A);

    // s2: rest of CSR build
    scan_pass1_dual<<<nbA + nbP, 256, 0, s2>>>(cntA, bsumA, N_A, cntP, bsumP, N_P, nbA);
    scan_pass2_dual<<<2, 128, 0, s2>>>(bsumA, nbA, bsumP, nbP);
    scan_pass3_dual<<<nbA + nbP, 256, 0, s2>>>(cntA, bsumA, pa_ptr, N_A,
                                               cntP, bsumP, ap_ptr, N_P, nbA);
    scatter_dual<<<dgrid, HB, 0, s2>>>(pa_row, pa_col, pa_val, pa_ptr, curA, pa_ccol, pa_cval,
                                       ap_row, ap_col, ap_val, ap_ptr, curP, ap_ccol, ap_cval);
    cudaEventRecord(eCsr, s2);

    // ---- main: P-A-P / P-A-P-A-P chains (fp16 operands) ----
    cudaStreamWaitEvent(0, eCsr, 0);
    spmm_csr_h<<<sgrid(N_A), 256>>>(pa_ptr, pa_ccol, pa_cval, zpH,  nullptr,  hH,   N_A);  // h
    spmm_csr_h<<<sgrid(N_P), 256>>>(ap_ptr, ap_ccol, ap_cval, hH,   out_pap,  papH, N_P);  // pap (fp32 + fp16)
    spmm_csr_h<<<sgrid(N_A), 256>>>(pa_ptr, pa_ccol, pa_cval, papH, nullptr,  hH,   N_A);  // h2
    spmm_csr_h<<<sgrid(N_P), 256>>>(ap_ptr, ap_ccol, ap_cval, hH,   out_papap, nullptr, N_P); // papap

    // ---- s3: A-P-A chain (concurrent) ----
    cudaStreamWaitEvent(s3, eCsr, 0);
    spmm_csr_h<<<sgrid(N_P), 256, 0, s3>>>(ap_ptr, ap_ccol, ap_cval, zaH, nullptr, gH,      N_P); // g
    spmm_csr_h<<<sgrid(N_A), 256, 0, s3>>>(pa_ptr, pa_ccol, pa_cval, gH,  out_apa, nullptr, N_A); // apa
    cudaEventRecord(eApa, s3);

    // ---- join ----
    cudaStreamWaitEvent(0, eApa, 0);
}

// round 17
// speedup vs baseline: 1.2555x; 1.0141x over previous
#include <cuda_runtime.h>
#include <cuda_bf16.h>
#include <cuda_fp16.h>
#include <cstdint>

#define N_P   200000
#define N_A   100000
#define D_MP  64
#define E_NNZ 1200000
#define F_P   256
#define F_A   128

// ===========================================================================
// Static scratch (fp16 operand matrices for SpMM gathers)
// ===========================================================================
__device__ __align__(16) __half g_zpH [(size_t)N_P * D_MP];  // zp
__device__ __align__(16) __half g_zaH [(size_t)N_A * D_MP];  // za
__device__ __align__(16) __half g_hH  [(size_t)N_A * D_MP];  // h, then h2
__device__ __align__(16) __half g_papH[(size_t)N_P * D_MP];  // pap fp16 copy
__device__ __align__(16) __half g_gH  [(size_t)N_P * D_MP];  // g

__device__ __align__(16) uint2 g_WsplitP[(F_P / 32) * 1024];
__device__ __align__(16) uint2 g_WsplitA[(F_A / 32) * 1024];

__device__ int   g_pa_ptr[N_A + 1];
__device__ int   g_ap_ptr[N_P + 1];
__device__ int   g_pa_ccol[E_NNZ];
__device__ float g_pa_cval[E_NNZ];
__device__ int   g_ap_ccol[E_NNZ];
__device__ float g_ap_cval[E_NNZ];
__device__ int   g_cnt[2 * (N_P + N_A)];
__device__ int   g_bsumA[128];
__device__ int   g_bsumP[128];

// ===========================================================================
// bf16 split helpers (GEMM)
// ===========================================================================
__device__ __forceinline__ uint2 split_pack(float a, float b) {
    float fa = __bfloat162float(__float2bfloat16_rn(a));
    float fb = __bfloat162float(__float2bfloat16_rn(b));
    uint32_t hi, lo;
    asm("cvt.rn.bf16x2.f32 %0, %1, %2;" : "=r"(hi) : "f"(fb), "f"(fa));
    asm("cvt.rn.bf16x2.f32 %0, %1, %2;" : "=r"(lo) : "f"(b - fb), "f"(a - fa));
    return make_uint2(hi, lo);
}

__device__ __forceinline__ void mma_bf16(float* d, const uint32_t* a, const uint32_t* b) {
    asm volatile("mma.sync.aligned.m16n8k16.row.col.f32.bf16.bf16.f32 "
                 "{%0,%1,%2,%3}, {%4,%5,%6,%7}, {%8,%9}, {%0,%1,%2,%3};"
                 : "+f"(d[0]), "+f"(d[1]), "+f"(d[2]), "+f"(d[3])
                 : "r"(a[0]), "r"(a[1]), "r"(a[2]), "r"(a[3]),
                   "r"(b[0]), "r"(b[1]));
}

// ===========================================================================
// Prep: split W into chunked smem-image layout
// ===========================================================================
__global__ void prep_W(const float* __restrict__ W, uint2* __restrict__ dst, int F) {
    int i = blockIdx.x * blockDim.x + threadIdx.x;
    int total = (F / 32) * 1024;
    if (i >= total) return;
    int chunk = i >> 10;
    int idx   = i & 1023;
    int nn = idx & 63;
    int kp = idx >> 6;
    int k  = chunk * 32 + kp * 2;
    float w0 = W[(size_t)k * 64 + nn];
    float w1 = W[(size_t)(k + 1) * 64 + nn];
    dst[i] = split_pack(w0, w1);
}

// ===========================================================================
// Tensor-core GEMM (R10/R11 proven config), fp16 output
// ===========================================================================
template<int F>
__global__ __launch_bounds__(256, 2) void gemm_bf16x3(const float* __restrict__ x,
                                                      const uint2* __restrict__ Wsp,
                                                      __half* __restrict__ out, int n) {
    constexpr int NC = F / 32;
    extern __shared__ uint2 smbuf[];
    uint2* wsb[2] = { smbuf,            smbuf + 64 * 20 };
    uint2* xsb[2] = { smbuf + 2 * 64 * 20, smbuf + 2 * 64 * 20 + 128 * 20 };

    const int t    = threadIdx.x;
    const int lane = t & 31;
    const int wid  = t >> 5;
    const int wm   = wid >> 1;
    const int wn   = wid & 1;
    const int tig  = lane & 3;
    const int gid  = lane >> 2;
    const int row0 = blockIdx.x * 128;

    float2 xreg[8];
    uint2  wreg[4];

    auto ldg_chunk = [&](int c) {
        const uint2* src = Wsp + c * 1024;
        #pragma unroll
        for (int j = 0; j < 4; j++) wreg[j] = __ldg(src + j * 256 + t);
        #pragma unroll
        for (int j = 0; j < 8; j++) {
            int idx = j * 256 + t;
            int r   = idx >> 4;
            int kp  = idx & 15;
            int grow = row0 + r;
            xreg[j] = (grow < n)
                ? *(const float2*)(x + (size_t)grow * F + c * 32 + kp * 2)
                : make_float2(0.f, 0.f);
        }
    };
    auto sts_chunk = [&](int b) {
        #pragma unroll
        for (int j = 0; j < 4; j++) {
            int idx = j * 256 + t;
            wsb[b][(idx & 63) * 20 + (idx >> 6)] = wreg[j];
        }
        #pragma unroll
        for (int j = 0; j < 8; j++) {
            int idx = j * 256 + t;
            xsb[b][(idx >> 4) * 20 + (idx & 15)] = split_pack(xreg[j].x, xreg[j].y);
        }
    };

    float acc[2][4][4];
    #pragma unroll
    for (int mt = 0; mt < 2; mt++)
        #pragma unroll
        for (int nt = 0; nt < 4; nt++)
            #pragma unroll
            for (int q = 0; q < 4; q++) acc[mt][nt][q] = 0.f;

    ldg_chunk(0);
    sts_chunk(0);
    if (NC > 1) ldg_chunk(1);
    __syncthreads();

    #pragma unroll
    for (int c = 0; c < NC; c++) {
        if (c + 1 < NC) sts_chunk((c + 1) & 1);
        if (c + 2 < NC) ldg_chunk(c + 2);

        const uint2* xs = xsb[c & 1];
        const uint2* ws = wsb[c & 1];

        #pragma unroll
        for (int ks = 0; ks < 2; ks++) {
            const int p0 = ks * 8 + tig;
            const int p1 = p0 + 4;

            uint32_t ah[2][4], al[2][4];
            #pragma unroll
            for (int mt = 0; mt < 2; mt++) {
                int r0 = wm * 32 + mt * 16 + gid;
                uint2 qa0 = xs[r0 * 20 + p0];
                uint2 qa1 = xs[(r0 + 8) * 20 + p0];
                uint2 qa2 = xs[r0 * 20 + p1];
                uint2 qa3 = xs[(r0 + 8) * 20 + p1];
                ah[mt][0] = qa0.x; ah[mt][1] = qa1.x; ah[mt][2] = qa2.x; ah[mt][3] = qa3.x;
                al[mt][0] = qa0.y; al[mt][1] = qa1.y; al[mt][2] = qa2.y; al[mt][3] = qa3.y;
            }

            #pragma unroll
            for (int nt = 0; nt < 4; nt++) {
                int nn = wn * 32 + nt * 8 + gid;
                uint2 qb0 = ws[nn * 20 + p0];
                uint2 qb1 = ws[nn * 20 + p1];
                uint32_t bh[2] = {qb0.x, qb1.x};
                uint32_t bl[2] = {qb0.y, qb1.y};
                #pragma unroll
                for (int mt = 0; mt < 2; mt++) {
                    mma_bf16(acc[mt][nt], ah[mt], bh);
                    mma_bf16(acc[mt][nt], al[mt], bh);
                    mma_bf16(acc[mt][nt], ah[mt], bl);
                }
            }
        }
        __syncthreads();
    }

    #pragma unroll
    for (int mt = 0; mt < 2; mt++) {
        #pragma unroll
        for (int half = 0; half < 2; half++) {
            int grow = row0 + wm * 32 + mt * 16 + gid + half * 8;
            if (grow < n) {
                __half* o = out + (size_t)grow * D_MP + wn * 32 + tig * 2;
                #pragma unroll
                for (int nt = 0; nt < 4; nt++) {
                    float2 v = half ? make_float2(acc[mt][nt][2], acc[mt][nt][3])
                                    : make_float2(acc[mt][nt][0], acc[mt][nt][1]);
                    *(__half2*)(o + nt * 8) = __floats2half2_rn(v.x, v.y);
                }
            }
        }
    }
}

// ===========================================================================
// CSR build
// ===========================================================================
__global__ void hist_dual(const int* __restrict__ rowA, const int* __restrict__ rowP,
                          int* __restrict__ cntA, int* __restrict__ cntP) {
    int i = blockIdx.x * blockDim.x + threadIdx.x;
    if (i < E_NNZ) {
        atomicAdd(&cntA[rowA[i]], 1);
    } else if (i < 2 * E_NNZ) {
        atomicAdd(&cntP[rowP[i - E_NNZ]], 1);
    }
}

#define SCAN_CHUNK 2048

__global__ void scan_pass1_dual(const int* __restrict__ cntA, int* __restrict__ bsA, int nA,
                                const int* __restrict__ cntP, int* __restrict__ bsP, int nP,
                                int nbA) {
    __shared__ int sh[256];
    const int* cnt = (blockIdx.x < nbA) ? cntA : cntP;
    int*       bs  = (blockIdx.x < nbA) ? bsA  : bsP;
    int        n   = (blockIdx.x < nbA) ? nA   : nP;
    int        blk = (blockIdx.x < nbA) ? blockIdx.x : blockIdx.x - nbA;
    int base = blk * SCAN_CHUNK;
    int t = threadIdx.x;
    int s = 0;
    #pragma unroll
    for (int j = 0; j < 8; j++) {
        int i = base + t * 8 + j;
        if (i < n) s += cnt[i];
    }
    sh[t] = s;
    __syncthreads();
    for (int off = 128; off > 0; off >>= 1) {
        if (t < off) sh[t] += sh[t + off];
        __syncthreads();
    }
    if (t == 0) bs[blk] = sh[0];
}

__global__ void scan_pass2_dual(int* __restrict__ bsA, int nbA,
                                int* __restrict__ bsP, int nbP) {
    __shared__ int sh[128];
    int* bs = blockIdx.x ? bsP : bsA;
    int nb  = blockIdx.x ? nbP : nbA;
    int t = threadIdx.x;
    int v = (t < nb) ? bs[t] : 0;
    sh[t] = v;
    __syncthreads();
    for (int off = 1; off < 128; off <<= 1) {
        int xx = (t >= off) ? sh[t - off] : 0;
        __syncthreads();
        sh[t] += xx;
        __syncthreads();
    }
    if (t < nb) bs[t] = sh[t] - v;
}

__global__ void scan_pass3_dual(const int* __restrict__ cntA, const int* __restrict__ bsA,
                                int* __restrict__ ptrA, int nA,
                                const int* __restrict__ cntP, const int* __restrict__ bsP,
                                int* __restrict__ ptrP, int nP, int nbA) {
    __shared__ int sh[256];
    const int* cnt = (blockIdx.x < nbA) ? cntA : cntP;
    const int* bs  = (blockIdx.x < nbA) ? bsA  : bsP;
    int*       ptr = (blockIdx.x < nbA) ? ptrA : ptrP;
    int        n   = (blockIdx.x < nbA) ? nA   : nP;
    int        blk = (blockIdx.x < nbA) ? blockIdx.x : blockIdx.x - nbA;
    int base = blk * SCAN_CHUNK;
    int t = threadIdx.x;
    int v[8];
    int s = 0;
    #pragma unroll
    for (int j = 0; j < 8; j++) {
        int i = base + t * 8 + j;
        v[j] = (i < n) ? cnt[i] : 0;
        s += v[j];
    }
    sh[t] = s;
    __syncthreads();
    for (int off = 1; off < 256; off <<= 1) {
        int xx = (t >= off) ? sh[t - off] : 0;
        __syncthreads();
        sh[t] += xx;
        __syncthreads();
    }
    int ex = sh[t] - s + bs[blk];
    #pragma unroll
    for (int j = 0; j < 8; j++) {
        int i = base + t * 8 + j;
        if (i < n) {
            ptr[i] = ex;
            ex += v[j];
            if (i == n - 1) ptr[n] = ex;
        }
    }
}

__global__ void scatter_dual(const int* __restrict__ rowA, const int* __restrict__ colA,
                             const float* __restrict__ valA,
                             const int* __restrict__ ptrA, int* __restrict__ curA,
                             int* __restrict__ ccolA, float* __restrict__ cvalA,
                             const int* __restrict__ rowP, const int* __restrict__ colP,
                             const float* __restrict__ valP,
                             const int* __restrict__ ptrP, int* __restrict__ curP,
                             int* __restrict__ ccolP, float* __restrict__ cvalP) {
    int i = blockIdx.x * blockDim.x + threadIdx.x;
    if (i < E_NNZ) {
        int r = rowA[i];
        int p = ptrA[r] + atomicAdd(&curA[r], 1);
        ccolA[p] = colA[i];
        cvalA[p] = valA[i];
    } else if (i < 2 * E_NNZ) {
        int j = i - E_NNZ;
        int r = rowP[j];
        int p = ptrP[r] + atomicAdd(&curP[r], 1);
        ccolP[p] = colP[j];
        cvalP[p] = valP[j];
    }
}

// ===========================================================================
// CSR SpMM, fp16 gather source (R16 proven)
// ===========================================================================
__global__ void spmm_csr_h(const int* __restrict__ ptr,
                           const int* __restrict__ ccol,
                           const float* __restrict__ cval,
                           const __half* __restrict__ z,
                           float* __restrict__ outF,
                           __half* __restrict__ outH, int nrows) {
    int w = (blockIdx.x * blockDim.x + threadIdx.x) >> 5;
    if (w >= nrows) return;
    int lane = threadIdx.x & 31;
    int half = lane >> 4;
    int s    = lane & 15;

    int beg = ptr[w], end = ptr[w + 1];
    float4 acc0 = make_float4(0.f, 0.f, 0.f, 0.f);
    float4 acc1 = make_float4(0.f, 0.f, 0.f, 0.f);

    int e = beg + half;
    for (; e + 2 < end; e += 4) {
        int   c0 = __ldg(ccol + e);
        float v0 = __ldg(cval + e);
        int   c1 = __ldg(ccol + e + 2);
        float v1 = __ldg(cval + e + 2);
        uint2 q0 = __ldg((const uint2*)(z + (size_t)c0 * D_MP) + s);
        uint2 q1 = __ldg((const uint2*)(z + (size_t)c1 * D_MP) + s);
        float2 a0 = __half22float2(*(__half2*)&q0.x);
        float2 b0 = __half22float2(*(__half2*)&q0.y);
        float2 a1 = __half22float2(*(__half2*)&q1.x);
        float2 b1 = __half22float2(*(__half2*)&q1.y);
        acc0.x = fmaf(v0, a0.x, acc0.x);
        acc0.y = fmaf(v0, a0.y, acc0.y);
        acc0.z = fmaf(v0, b0.x, acc0.z);
        acc0.w = fmaf(v0, b0.y, acc0.w);
        acc1.x = fmaf(v1, a1.x, acc1.x);
        acc1.y = fmaf(v1, a1.y, acc1.y);
        acc1.z = fmaf(v1, b1.x, acc1.z);
        acc1.w = fmaf(v1, b1.y, acc1.w);
    }
    if (e < end) {
        int   c = __ldg(ccol + e);
        float v = __ldg(cval + e);
        uint2 q = __ldg((const uint2*)(z + (size_t)c * D_MP) + s);
        float2 a = __half22float2(*(__half2*)&q.x);
        float2 b = __half22float2(*(__half2*)&q.y);
        acc0.x = fmaf(v, a.x, acc0.x);
        acc0.y = fmaf(v, a.y, acc0.y);
        acc0.z = fmaf(v, b.x, acc0.z);
        acc0.w = fmaf(v, b.y, acc0.w);
    }
    acc0.x += acc1.x; acc0.y += acc1.y; acc0.z += acc1.z; acc0.w += acc1.w;

    acc0.x += __shfl_xor_sync(0xffffffffu, acc0.x, 16);
    acc0.y += __shfl_xor_sync(0xffffffffu, acc0.y, 16);
    acc0.z += __shfl_xor_sync(0xffffffffu, acc0.z, 16);
    acc0.w += __shfl_xor_sync(0xffffffffu, acc0.w, 16);
    if (half == 0) {
        if (outF)
            *((float4*)(outF + (size_t)w * D_MP) + s) = acc0;
        if (outH) {
            uint2 q;
            *(__half2*)&q.x = __floats2half2_rn(acc0.x, acc0.y);
            *(__half2*)&q.y = __floats2half2_rn(acc0.z, acc0.w);
            *((uint2*)(outH + (size_t)w * D_MP) + s) = q;
        }
    }
}

// ===========================================================================
// Launch — NEW schedule: gemm A first (main), A-P-A chain hidden under gemm P
// ===========================================================================
extern "C" void kernel_launch(void* const* d_in, const int* in_sizes, int n_in,
                              void* d_out, int out_size) {
    const float* x_paper  = (const float*)d_in[0];
    const float* x_author = (const float*)d_in[1];
    const float* W_paper  = (const float*)d_in[2];
    const float* W_author = (const float*)d_in[3];
    const int*   pa_row   = (const int*)  d_in[4];
    const int*   pa_col   = (const int*)  d_in[5];
    const float* pa_val   = (const float*)d_in[6];
    const int*   ap_row   = (const int*)  d_in[7];
    const int*   ap_col   = (const int*)  d_in[8];
    const float* ap_val   = (const float*)d_in[9];

    float* out       = (float*)d_out;
    float* out_pap   = out;
    float* out_papap = out + (size_t)N_P * D_MP;
    float* out_apa   = out + (size_t)2 * N_P * D_MP;

    __half *zpH, *zaH, *hH, *papH, *gH;
    uint2 *WspP, *WspA;
    int *pa_ptr, *ap_ptr, *pa_ccol, *ap_ccol, *cnt, *bsumA, *bsumP;
    float *pa_cval, *ap_cval;
    cudaGetSymbolAddress((void**)&zpH,     g_zpH);
    cudaGetSymbolAddress((void**)&zaH,     g_zaH);
    cudaGetSymbolAddress((void**)&hH,      g_hH);
    cudaGetSymbolAddress((void**)&papH,    g_papH);
    cudaGetSymbolAddress((void**)&gH,      g_gH);
    cudaGetSymbolAddress((void**)&WspP,    g_WsplitP);
    cudaGetSymbolAddress((void**)&WspA,    g_WsplitA);
    cudaGetSymbolAddress((void**)&pa_ptr,  g_pa_ptr);
    cudaGetSymbolAddress((void**)&ap_ptr,  g_ap_ptr);
    cudaGetSymbolAddress((void**)&pa_ccol, g_pa_ccol);
    cudaGetSymbolAddress((void**)&pa_cval, g_pa_cval);
    cudaGetSymbolAddress((void**)&ap_ccol, g_ap_ccol);
    cudaGetSymbolAddress((void**)&ap_cval, g_ap_cval);
    cudaGetSymbolAddress((void**)&cnt,     g_cnt);
    cudaGetSymbolAddress((void**)&bsumA,   g_bsumA);
    cudaGetSymbolAddress((void**)&bsumP,   g_bsumP);

    int* cntA = cnt;
    int* curA = cnt + N_A;
    int* cntP = cnt + 2 * N_A;
    int* curP = cnt + 2 * N_A + N_P;

    static cudaStream_t s2 = nullptr, s3 = nullptr;
    static cudaEvent_t eFork, eCsr, eGemmA, eApa;
    if (s2 == nullptr) {
        cudaStreamCreateWithFlags(&s2, cudaStreamNonBlocking);
        cudaStreamCreateWithFlags(&s3, cudaStreamNonBlocking);
        cudaEventCreateWithFlags(&eFork,  cudaEventDisableTiming);
        cudaEventCreateWithFlags(&eCsr,   cudaEventDisableTiming);
        cudaEventCreateWithFlags(&eGemmA, cudaEventDisableTiming);
        cudaEventCreateWithFlags(&eApa,   cudaEventDisableTiming);
    }

    const int GEMM_SMEM = (2 * 64 * 20 + 2 * 128 * 20) * (int)sizeof(uint2);  // 61440
    cudaFuncSetAttribute(gemm_bf16x3<F_P>, cudaFuncAttributeMaxDynamicSharedMemorySize, GEMM_SMEM);
    cudaFuncSetAttribute(gemm_bf16x3<F_A>, cudaFuncAttributeMaxDynamicSharedMemorySize, GEMM_SMEM);

    const int HB = 256;
    const int dgrid = (2 * E_NNZ + HB - 1) / HB;
    const int nbA = (N_A + SCAN_CHUNK - 1) / SCAN_CHUNK;
    const int nbP = (N_P + SCAN_CHUNK - 1) / SCAN_CHUNK;
    auto sgrid = [](int nrows) { return (nrows * 32 + 255) / 256; };

    // ---- fork ----
    cudaEventRecord(eFork, 0);
    cudaStreamWaitEvent(s2, eFork, 0);

    cudaMemsetAsync(cnt, 0, (size_t)2 * (N_P + N_A) * sizeof(int), s2);

    // main: prep (k0, k1), gemm A (k2), gemm P (k3 <- ncu capture slot)
    prep_W<<<(F_P / 32 * 1024 + 255) / 256, 256>>>(W_paper,  WspP, F_P);
    prep_W<<<(F_A / 32 * 1024 + 255) / 256, 256>>>(W_author, WspA, F_A);
    gemm_bf16x3<F_A><<<(N_A + 127) / 128, 256, GEMM_SMEM>>>(x_author, WspA, zaH, N_A);
    cudaEventRecord(eGemmA, 0);
    gemm_bf16x3<F_P><<<(N_P + 127) / 128, 256, GEMM_SMEM>>>(x_paper, WspP, zpH, N_P);

    // s2: CSR build (concurrent with gemms)
    hist_dual<<<dgrid, HB, 0, s2>>>(pa_row, ap_row, cntA, cntP);
    scan_pass1_dual<<<nbA + nbP, 256, 0, s2>>>(cntA, bsumA, N_A, cntP, bsumP, N_P, nbA);
    scan_pass2_dual<<<2, 128, 0, s2>>>(bsumA, nbA, bsumP, nbP);
    scan_pass3_dual<<<nbA + nbP, 256, 0, s2>>>(cntA, bsumA, pa_ptr, N_A,
                                               cntP, bsumP, ap_ptr, N_P, nbA);
    scatter_dual<<<dgrid, HB, 0, s2>>>(pa_row, pa_col, pa_val, pa_ptr, curA, pa_ccol, pa_cval,
                                       ap_row, ap_col, ap_val, ap_ptr, curP, ap_ccol, ap_cval);
    cudaEventRecord(eCsr, s2);

    // s3: A-P-A chain hidden under gemm P (needs za + CSR only)
    cudaStreamWaitEvent(s3, eGemmA, 0);
    cudaStreamWaitEvent(s3, eCsr, 0);
    spmm_csr_h<<<sgrid(N_P), 256, 0, s3>>>(ap_ptr, ap_ccol, ap_cval, zaH, nullptr, gH,      N_P); // g
    spmm_csr_h<<<sgrid(N_A), 256, 0, s3>>>(pa_ptr, pa_ccol, pa_cval, gH,  out_apa, nullptr, N_A); // apa
    cudaEventRecord(eApa, s3);

    // main: P-A-P / P-A-P-A-P chains (after gemm P, in-order on main)
    cudaStreamWaitEvent(0, eCsr, 0);
    spmm_csr_h<<<sgrid(N_A), 256>>>(pa_ptr, pa_ccol, pa_cval, zpH,  nullptr,   hH,   N_A);  // h
    spmm_csr_h<<<sgrid(N_P), 256>>>(ap_ptr, ap_ccol, ap_cval, hH,   out_pap,   papH, N_P);  // pap
    spmm_csr_h<<<sgrid(N_A), 256>>>(pa_ptr, pa_ccol, pa_cval, papH, nullptr,   hH,   N_A);  // h2
    spmm_csr_h<<<sgrid(N_P), 256>>>(ap_ptr, ap_ccol, ap_cval, hH,   out_papap, nullptr, N_P); // papap

    // ---- join ----
    cudaStreamWaitEvent(0, eApa, 0);
}